// round 17
// baseline (speedup 1.0000x reference)
#include <cuda_runtime.h>
#include <cuda_fp16.h>
#include <cstdint>

// ============================================================================
// Head_13: fused causal single-head attention. B=1024 T=128 C=384 HS=64 fp32.
// Warp-specialized phase 1: 12 consumer warps (MMA only; 4 row-blocks x
// {Q,K,V}) + 4 producer warps (x LDG->fp16->STS, W cp.async prefetch),
// synced with named barriers (X double-buffered, W write-once region).
// S: Q hi/lo x K (2 MMAs), softmax via raw ex2 (log2-domain Q, no max pass).
// O: P x V (1 MMA, ldmatrix.trans). Balanced causal warp mapping {wm, 7-wm}.
// One CTA per batch, 512 threads.
// ============================================================================

#define T_DIM 128
#define H_DIM 64

// row strides (bytes) — padded, conflict-free for ldmatrix
#define XSTR 144   // 64 fp16 + 16B pad
#define WSTR 144
#define QSTR 144
#define PSTR 272   // 128 fp16 + 16B pad

// ---- smem offsets (phase 1) ----
#define XH0_OFF 0
#define XH1_OFF 18432
#define W_OFF   36864           // full W image: 6*27648 = 165888
#define SMEM_TOTAL 202752
// ---- post-phase-1 overlay (dead X/W region; gated by consumer barrier) ----
#define QH_OFF  0
#define QL_OFF  18432
#define KH_OFF  36864
#define V_OFF   55296           // V row-major [128][64], stride 144
#define PART_OFF 73728          // 128 rows x 4 wn x float = 2048
#define PH_OFF  0               // P overlays QH/QL (34816 <= 36864)

// named barrier ids
#define NB_F0 1
#define NB_F1 2
#define NB_E0 3
#define NB_E1 4
#define NB_CONS 5

// fp16 weight image: 6 chunks x [192 rows x 144B]
__device__ __align__(16) unsigned char g_wh[6 * 27648];

// 0.125 * log2(e): folds softmax scale AND exp->ex2 conversion into Q
#define QSCALE 0.18033688011112042f

// ---------------------------------------------------------------------------
__device__ __forceinline__ uint32_t smem_u32(const void* p) {
    uint32_t a;
    asm("{ .reg .u64 t; cvta.to.shared.u64 t, %1; cvt.u32.u64 %0, t; }"
        : "=r"(a) : "l"(p));
    return a;
}
__device__ __forceinline__ uint32_t h2pack(float a, float b) {
    __half2 h = __floats2half2_rn(a, b);
    return *reinterpret_cast<uint32_t*>(&h);
}
__device__ __forceinline__ void split2x2(float a, float b, uint32_t& hi, uint32_t& lo) {
    __half2 h = __floats2half2_rn(a, b);
    float2 hf = __half22float2(h);
    __half2 l = __floats2half2_rn(a - hf.x, b - hf.y);
    hi = *reinterpret_cast<uint32_t*>(&h);
    lo = *reinterpret_cast<uint32_t*>(&l);
}
__device__ __forceinline__ float ex2(float v) {
    float r;
    asm("ex2.approx.f32 %0, %1;" : "=f"(r) : "f"(v));
    return r;
}
__device__ __forceinline__ float rcpa(float v) {
    float r;
    asm("rcp.approx.f32 %0, %1;" : "=f"(r) : "f"(v));
    return r;
}
__device__ __forceinline__ void ldmx4(uint32_t* r, uint32_t addr) {
    asm volatile("ldmatrix.sync.aligned.m8n8.x4.shared.b16 {%0,%1,%2,%3}, [%4];"
                 : "=r"(r[0]), "=r"(r[1]), "=r"(r[2]), "=r"(r[3]) : "r"(addr));
}
__device__ __forceinline__ void ldmx4t(uint32_t* r, uint32_t addr) {
    asm volatile("ldmatrix.sync.aligned.m8n8.x4.trans.shared.b16 {%0,%1,%2,%3}, [%4];"
                 : "=r"(r[0]), "=r"(r[1]), "=r"(r[2]), "=r"(r[3]) : "r"(addr));
}
__device__ __forceinline__ void mma16816(float* d, const uint32_t* a, const uint32_t* b) {
    asm volatile(
        "mma.sync.aligned.m16n8k16.row.col.f32.f16.f16.f32 "
        "{%0,%1,%2,%3}, {%4,%5,%6,%7}, {%8,%9}, {%0,%1,%2,%3};"
        : "+f"(d[0]), "+f"(d[1]), "+f"(d[2]), "+f"(d[3])
        : "r"(a[0]), "r"(a[1]), "r"(a[2]), "r"(a[3]), "r"(b[0]), "r"(b[1]));
}
__device__ __forceinline__ void cp16(uint32_t saddr, const void* g) {
    asm volatile("cp.async.cg.shared.global [%0], [%1], 16;"
                 :: "r"(saddr), "l"(g));
}
#define CP_COMMIT() asm volatile("cp.async.commit_group;" ::: "memory")
#define CP_WAIT0()  asm volatile("cp.async.wait_group 0;" ::: "memory")
#define CP_WAIT1()  asm volatile("cp.async.wait_group 1;" ::: "memory")
#define CP_WAIT2()  asm volatile("cp.async.wait_group 2;" ::: "memory")

#define NBAR_SYNC(id, cnt)   asm volatile("bar.sync %0, %1;"   :: "r"(id), "r"(cnt) : "memory")
#define NBAR_ARRIVE(id, cnt) asm volatile("bar.arrive %0, %1;" :: "r"(id), "r"(cnt) : "memory")

// B-operand pair address for ldmatrix.x4 (two adjacent 8-col groups, K-major)
__device__ __forceinline__ uint32_t baddr(uint32_t base, int colbase, int ks,
                                          int lane, int stride) {
    return base + (uint32_t)(colbase + (lane & 7) + ((lane >> 4) & 1) * 8) * stride
         + ks * 32 + ((lane >> 3) & 1) * 16;
}
// A-operand address for ldmatrix.x4 (m16 x k16, row-major)
__device__ __forceinline__ uint32_t aaddr(uint32_t base, int rowbase, int ks,
                                          int lane, int stride) {
    return base + (uint32_t)(rowbase + (lane & 15)) * stride
         + ks * 32 + (lane >> 4) * 16;
}
// trans B-operand address: source row-major [k(s)][n(h)]
__device__ __forceinline__ uint32_t taddr(uint32_t base, int colbase, int ks,
                                          int lane, int stride) {
    int s = ks * 16 + ((lane >> 3) & 1) * 8 + (lane & 7);
    int h = colbase + ((lane >> 4) & 1) * 8;
    return base + (uint32_t)s * stride + h * 2;
}

// ---------------------------------------------------------------------------
// Prep: stacked transposed weights Wt[192][384] -> fp16, padded chunk images.
// ---------------------------------------------------------------------------
__global__ void prep_kernel(const float* __restrict__ Wq,
                            const float* __restrict__ Wk,
                            const float* __restrict__ Wv) {
    int idx = blockIdx.x * 256 + threadIdx.x;
    if (idx >= 192 * 384) return;
    int n = idx / 384, c = idx % 384;
    float w;
    if (n < 64)       w = Wq[c * 64 + n];
    else if (n < 128) w = Wk[c * 64 + (n - 64)];
    else              w = Wv[c * 64 + (n - 128)];
    int chunk = c >> 6, j = c & 63;
    uint32_t off = (uint32_t)chunk * 27648u + (uint32_t)n * WSTR + j * 2;
    *(unsigned short*)(g_wh + off) = __half_as_ushort(__float2half_rn(w));
}

// ---------------------------------------------------------------------------
__global__ void __launch_bounds__(512, 1)
attn_kernel(const float* __restrict__ x, float* __restrict__ out) {
    extern __shared__ __align__(16) char sm[];
    const uint32_t smb = smem_u32(sm);
    const int tid  = threadIdx.x;
    const int lane = tid & 31;
    const int w    = tid >> 5;
    const int b    = blockIdx.x;
    const float* xb = x + (size_t)b * (T_DIM * 384);

    // ================= phase 1 (warp-specialized): [Q|K|V] = x @ Wt^T =======
    if (w < 12) {
        // ---------------- consumers: MMA only ----------------
        const int cwm = w & 3;       // row block (32 rows)
        const int cwn = w >> 2;      // matrix: 0=Q, 1=K, 2=V (64 cols)
        float acc[2][8][4];
#pragma unroll
        for (int i = 0; i < 2; i++)
#pragma unroll
            for (int j = 0; j < 8; j++)
#pragma unroll
                for (int k = 0; k < 4; k++) acc[i][j][k] = 0.f;

        for (int c = 0; c < 6; c++) {
            NBAR_SYNC(NB_F0 + (c & 1), 512);
            const uint32_t xba = smb + ((c & 1) ? XH1_OFF : XH0_OFF);
            const uint32_t wba = smb + W_OFF + (uint32_t)c * 27648u;
#pragma unroll
            for (int ks = 0; ks < 4; ks++) {
                uint32_t ah[2][4], bh[4][4];
                ldmx4(ah[0], aaddr(xba, cwm * 32,      ks, lane, XSTR));
                ldmx4(ah[1], aaddr(xba, cwm * 32 + 16, ks, lane, XSTR));
#pragma unroll
                for (int np = 0; np < 4; np++)
                    ldmx4(bh[np], baddr(wba, cwn * 64 + np * 16, ks, lane, WSTR));
#pragma unroll
                for (int np = 0; np < 4; np++)
#pragma unroll
                    for (int half = 0; half < 2; half++) {
                        int nt = np * 2 + half;
                        mma16816(acc[0][nt], ah[0], bh[np] + half * 2);
                        mma16816(acc[1][nt], ah[1], bh[np] + half * 2);
                    }
            }
            if (c < 4) NBAR_ARRIVE(NB_E0 + (c & 1), 512);
        }

        // all consumers done before overlaying dead X/W region
        NBAR_SYNC(NB_CONS, 384);

        // writeback: Q (x QSCALE, hi/lo) / K (fp16) / V (row-major fp16)
        const int rb0c = cwm * 32 + (lane >> 2);
        if (cwn == 0) {
#pragma unroll
            for (int mt = 0; mt < 2; mt++) {
                int r = rb0c + mt * 16;
#pragma unroll
                for (int nt = 0; nt < 8; nt++) {
                    int gc = nt * 8 + 2 * (lane & 3);
                    uint32_t h01, l01, h23, l23;
                    split2x2(acc[mt][nt][0] * QSCALE, acc[mt][nt][1] * QSCALE, h01, l01);
                    split2x2(acc[mt][nt][2] * QSCALE, acc[mt][nt][3] * QSCALE, h23, l23);
                    *(uint32_t*)(sm + QH_OFF + (uint32_t)r * QSTR + gc * 2)       = h01;
                    *(uint32_t*)(sm + QL_OFF + (uint32_t)r * QSTR + gc * 2)       = l01;
                    *(uint32_t*)(sm + QH_OFF + (uint32_t)(r + 8) * QSTR + gc * 2) = h23;
                    *(uint32_t*)(sm + QL_OFF + (uint32_t)(r + 8) * QSTR + gc * 2) = l23;
                }
            }
        } else if (cwn == 1) {
#pragma unroll
            for (int mt = 0; mt < 2; mt++) {
                int r = rb0c + mt * 16;
#pragma unroll
                for (int nt = 0; nt < 8; nt++) {
                    int gc = nt * 8 + 2 * (lane & 3);
                    *(uint32_t*)(sm + KH_OFF + (uint32_t)r * QSTR + gc * 2) =
                        h2pack(acc[mt][nt][0], acc[mt][nt][1]);
                    *(uint32_t*)(sm + KH_OFF + (uint32_t)(r + 8) * QSTR + gc * 2) =
                        h2pack(acc[mt][nt][2], acc[mt][nt][3]);
                }
            }
        } else {
#pragma unroll
            for (int mt = 0; mt < 2; mt++) {
                int r = rb0c + mt * 16;
#pragma unroll
                for (int nt = 0; nt < 8; nt++) {
                    int gc = nt * 8 + 2 * (lane & 3);
                    *(uint32_t*)(sm + V_OFF + (uint32_t)r * QSTR + gc * 2) =
                        h2pack(acc[mt][nt][0], acc[mt][nt][1]);
                    *(uint32_t*)(sm + V_OFF + (uint32_t)(r + 8) * QSTR + gc * 2) =
                        h2pack(acc[mt][nt][2], acc[mt][nt][3]);
                }
            }
        }
    } else {
        // ---------------- producers: x stream + W prefetch ----------------
        const int ptid = tid - 384;   // 0..127
        const char* gw = (const char*)g_wh;
        // W chunks 0,1 (two cp.async groups)
        for (int i = ptid; i < 1728; i += 128)
            cp16(smb + W_OFF + i * 16, gw + i * 16);
        CP_COMMIT();
        for (int i = ptid; i < 1728; i += 128)
            cp16(smb + W_OFF + 27648 + i * 16, gw + 27648 + i * 16);
        CP_COMMIT();
        // x chunk 0 into regs
        float4 xr[16];
        const float4* xf = (const float4*)xb;
#pragma unroll
        for (int it = 0; it < 16; it++) {
            int i = ptid + it * 128;
            xr[it] = xf[(i >> 4) * 96 + (i & 15)];
        }

        for (int c = 0; c < 6; c++) {
            if (c >= 2) NBAR_SYNC(NB_E0 + (c & 1), 512);
            // prefetch W chunk c+2 (write-once region; consumers are at <= c+1)
            if (c < 4) {
                uint32_t doff = (uint32_t)(c + 2) * 27648u;
                for (int i = ptid; i < 1728; i += 128)
                    cp16(smb + W_OFF + doff + i * 16, gw + doff + i * 16);
                CP_COMMIT();
            }
            // convert x chunk c -> fp16 smem
            char* xd = sm + ((c & 1) ? XH1_OFF : XH0_OFF);
#pragma unroll
            for (int it = 0; it < 16; it++) {
                int i = ptid + it * 128;
                int t = i >> 4, f4 = i & 15;
                float4 v = xr[it];
                *(uint2*)(xd + (uint32_t)t * XSTR + f4 * 8) =
                    make_uint2(h2pack(v.x, v.y), h2pack(v.z, v.w));
            }
            // ensure W chunk c landed (outstanding: W(c+1), W(c+2))
            if (c < 4)      { CP_WAIT2(); }
            else if (c < 5) { CP_WAIT1(); }
            else            { CP_WAIT0(); }
            NBAR_ARRIVE(NB_F0 + (c & 1), 512);
            // prefetch x chunk c+1 regs (stall absorbed by consumer MMAs)
            if (c < 5) {
#pragma unroll
                for (int it = 0; it < 16; it++) {
                    int i = ptid + it * 128;
                    xr[it] = xf[(i >> 4) * 96 + (c + 1) * 16 + (i & 15)];
                }
            }
        }
    }
    __syncthreads();

    // ====== S = Q K^T, balanced: warp wm owns row blocks {wm, 7-wm} ======
    const int wm = w >> 2;
    const int wn = w & 3;
    const int base0 = wm * 16;          // mt0 rows
    const int base1 = 112 - wm * 16;    // mt1 rows
    const int rowmax0 = base0 + 15;
    const int rowmax1 = base1 + 15;
    float sacc[2][4][4];
#pragma unroll
    for (int i = 0; i < 2; i++)
#pragma unroll
        for (int j = 0; j < 4; j++)
#pragma unroll
            for (int k = 0; k < 4; k++) sacc[i][j][k] = 0.f;

    {
        const bool any0 = (wn * 16 <= rowmax0);
        const bool actB0 = (wn * 16 <= rowmax1);
        const bool actB1 = (64 + wn * 16 <= rowmax1);
#pragma unroll
        for (int ks = 0; ks < 4; ks++) {
            uint32_t qh[2][4], ql[2][4], kh[2][4];
            if (any0) {
                ldmx4(qh[0], aaddr(smb + QH_OFF, base0, ks, lane, QSTR));
                ldmx4(ql[0], aaddr(smb + QL_OFF, base0, ks, lane, QSTR));
            }
            ldmx4(qh[1], aaddr(smb + QH_OFF, base1, ks, lane, QSTR));
            ldmx4(ql[1], aaddr(smb + QL_OFF, base1, ks, lane, QSTR));
            if (actB0) ldmx4(kh[0], baddr(smb + KH_OFF, wn * 16,      ks, lane, QSTR));
            if (actB1) ldmx4(kh[1], baddr(smb + KH_OFF, 64 + wn * 16, ks, lane, QSTR));
#pragma unroll
            for (int np = 0; np < 2; np++) {
                int colbase = np * 64 + wn * 16;
                if (colbase <= rowmax1) {
#pragma unroll
                    for (int half = 0; half < 2; half++) {
                        int nt = np * 2 + half;
                        if (colbase <= rowmax0) {
                            mma16816(sacc[0][nt], qh[0], kh[np] + half * 2);
                            mma16816(sacc[0][nt], ql[0], kh[np] + half * 2);
                        }
                        mma16816(sacc[1][nt], qh[1], kh[np] + half * 2);
                        mma16816(sacc[1][nt], ql[1], kh[np] + half * 2);
                    }
                }
            }
        }
    }

    // ---- softmax (no max pass; logits in log2 domain): ex2, sum, merge ----
#pragma unroll
    for (int ri = 0; ri < 4; ri++) {
        int mt = ri >> 1, hb = ri & 1;
        int r = (mt ? base1 : base0) + (lane >> 2) + hb * 8;
        float s = 0.f;
#pragma unroll
        for (int nt = 0; nt < 4; nt++) {
            int c = (nt >> 1) * 64 + wn * 16 + (nt & 1) * 8 + 2 * (lane & 3);
#pragma unroll
            for (int vv = 0; vv < 2; vv++) {
                float val = (c + vv <= r) ? sacc[mt][nt][hb * 2 + vv] : -1e4f;
                float e = ex2(val);
                sacc[mt][nt][hb * 2 + vv] = e;
                s += e;
            }
        }
        s += __shfl_xor_sync(0xFFFFFFFFu, s, 1);
        s += __shfl_xor_sync(0xFFFFFFFFu, s, 2);
        if ((lane & 3) == 0)
            *(float*)(sm + PART_OFF + ((uint32_t)r * 4 + wn) * 4) = s;
    }
    __syncthreads();

    // merge partial sums, write P (single fp16) — overlays dead Q region
#pragma unroll
    for (int ri = 0; ri < 4; ri++) {
        int mt = ri >> 1, hb = ri & 1;
        int r = (mt ? base1 : base0) + (lane >> 2) + hb * 8;
        float4 p = *(const float4*)(sm + PART_OFF + (uint32_t)r * 16);
        float fac = rcpa((p.x + p.y) + (p.z + p.w));
#pragma unroll
        for (int nt = 0; nt < 4; nt++) {
            int c = (nt >> 1) * 64 + wn * 16 + (nt & 1) * 8 + 2 * (lane & 3);
            *(uint32_t*)(sm + PH_OFF + (uint32_t)r * PSTR + c * 2) =
                h2pack(sacc[mt][nt][hb * 2] * fac, sacc[mt][nt][hb * 2 + 1] * fac);
        }
    }
    __syncthreads();

    // ===== O = P V (balanced rows; V via ldmatrix.trans; 1-MMA) =====
    {
        float oacc[2][2][4];
#pragma unroll
        for (int i = 0; i < 2; i++)
#pragma unroll
            for (int j = 0; j < 2; j++)
#pragma unroll
                for (int k = 0; k < 4; k++) oacc[i][j][k] = 0.f;

#pragma unroll
        for (int ks = 0; ks < 8; ks++) {
            bool a0 = (ks <= wm);
            bool a1 = (ks <= 7 - wm);
            if (a0 || a1) {
                uint32_t ph[2][4], vh[4];
                if (a0) ldmx4(ph[0], aaddr(smb + PH_OFF, base0, ks, lane, PSTR));
                if (a1) ldmx4(ph[1], aaddr(smb + PH_OFF, base1, ks, lane, PSTR));
                ldmx4t(vh, taddr(smb + V_OFF, wn * 16, ks, lane, QSTR));
#pragma unroll
                for (int half = 0; half < 2; half++) {
                    if (a0) mma16816(oacc[0][half], ph[0], vh + half * 2);
                    if (a1) mma16816(oacc[1][half], ph[1], vh + half * 2);
                }
            }
        }
        // epilogue: fragments -> gmem
#pragma unroll
        for (int mt = 0; mt < 2; mt++) {
            int r = (mt ? base1 : base0) + (lane >> 2);
#pragma unroll
            for (int nt = 0; nt < 2; nt++) {
                int c = wn * 16 + nt * 8 + 2 * (lane & 3);
                size_t o = ((size_t)b * T_DIM + r) * H_DIM + c;
                *(float2*)(out + o)             = make_float2(oacc[mt][nt][0], oacc[mt][nt][1]);
                *(float2*)(out + o + 8 * H_DIM) = make_float2(oacc[mt][nt][2], oacc[mt][nt][3]);
            }
        }
    }
}

// ---------------------------------------------------------------------------
extern "C" void kernel_launch(void* const* d_in, const int* in_sizes, int n_in,
                              void* d_out, int out_size) {
    const float* x  = (const float*)d_in[0];
    const float* Wq = (const float*)d_in[1];
    const float* Wk = (const float*)d_in[2];
    const float* Wv = (const float*)d_in[3];
    float* out = (float*)d_out;

    cudaFuncSetAttribute(attn_kernel,
                         cudaFuncAttributeMaxDynamicSharedMemorySize, SMEM_TOTAL);

    prep_kernel<<<(192 * 384 + 255) / 256, 256>>>(Wq, Wk, Wv);
    attn_kernel<<<1024, 512, SMEM_TOTAL>>>(x, out);
}